// round 9
// baseline (speedup 1.0000x reference)
#include <cuda_runtime.h>
#include <cuda_fp16.h>

// Problem constants
#define T_STEPS 256
#define HID     256
#define BATCH   1024
#define LATD    128
#define OUTD    64
#define BC      8      // batch rows per CTA
#define NCTA    (BATCH / BC)  // 128

// -------- persistent scratch (no allocations allowed) --------
// fp16 transposed, gate-interleaved weights:
//   g_w0h[k*256 + j] = half4{ W[j][k], W[j+256][k], W[j+512][k], W[j+768][k] } packed as uint2
__device__ uint2  g_w0h[256 * 256];           // 512 KB
__device__ uint2  g_w1h[512 * 256];           // 1 MB  ([Wih1;Whh1] rows k=0..511)
__device__ __half g_woth[256 * 64];           // w_out transposed [k][o], fp16
__device__ float  g_gx0[BATCH * 1024];        // latent@Wih0^T + b_ih0 + b_hh0 (fp32, exact)
__device__ float  g_hinit[BATCH * 512];       // [b][layer*256 + j]
__device__ float  g_cinit[BATCH * 512];

// -------- packed f32x2 helpers (sm_103a FFMA2 path) --------
typedef unsigned long long ull;
__device__ __forceinline__ ull pk2(float a, float b) {
    ull r; asm("mov.b64 %0, {%1, %2};" : "=l"(r) : "f"(a), "f"(b)); return r;
}
__device__ __forceinline__ void upk2(ull v, float& a, float& b) {
    asm("mov.b64 {%0, %1}, %2;" : "=f"(a), "=f"(b) : "l"(v));
}
__device__ __forceinline__ ull dup2f(float a) {
    ull r; asm("mov.b64 %0, {%1, %1};" : "=l"(r) : "f"(a)); return r;
}
__device__ __forceinline__ ull fma2(ull a, ull b, ull c) {
    ull d; asm("fma.rn.f32x2 %0, %1, %2, %3;" : "=l"(d) : "l"(a), "l"(b), "l"(c)); return d;
}

__device__ __forceinline__ float sigf(float x) {
    return __fdividef(1.f, 1.f + __expf(-x));
}
__device__ __forceinline__ float tanh_fast(float x) {
    x = fminf(fmaxf(x, -15.f), 15.f);
    float e = __expf(2.f * x);
    return __fdividef(e - 1.f, e + 1.f);
}

// elementwise LSTM cell update for a packed batch pair
__device__ __forceinline__ void lstm_cell(ull gi, ull gf, ull gg, ull go,
                                          ull& cp, float& ha, float& hb) {
    float ia, ib, fa, fb, ga, gb, oa, ob, ca, cb;
    upk2(gi, ia, ib); upk2(gf, fa, fb); upk2(gg, ga, gb); upk2(go, oa, ob);
    upk2(cp, ca, cb);
    float cna = sigf(fa) * ca + sigf(ia) * tanh_fast(ga);
    float cnb = sigf(fb) * cb + sigf(ib) * tanh_fast(gb);
    ha = sigf(oa) * tanh_fast(cna);
    hb = sigf(ob) * tanh_fast(cnb);
    cp = pk2(cna, cnb);
}

// expand fp16 weight quad (uint2) into 4 duplicated f32x2 operands
__device__ __forceinline__ void wexp(uint2 wp, ull& wx, ull& wy, ull& wz, ull& ww) {
    float2 fxy = __half22float2(*reinterpret_cast<const __half2*>(&wp.x));
    float2 fzw = __half22float2(*reinterpret_cast<const __half2*>(&wp.y));
    wx = dup2f(fxy.x); wy = dup2f(fxy.y); wz = dup2f(fzw.x); ww = dup2f(fzw.y);
}

// ================= prep kernels =================

__global__ void tr_w0(const float* __restrict__ w_hh0) {
    int idx = blockIdx.x * blockDim.x + threadIdx.x;   // 65536
    int t = idx & 255, k = idx >> 8;
    __half2 a = __floats2half2_rn(w_hh0[t * 256 + k],         w_hh0[(t + 256) * 256 + k]);
    __half2 b = __floats2half2_rn(w_hh0[(t + 512) * 256 + k], w_hh0[(t + 768) * 256 + k]);
    g_w0h[k * 256 + t] = make_uint2(*reinterpret_cast<uint*>(&a),
                                    *reinterpret_cast<uint*>(&b));
}

__global__ void tr_w1(const float* __restrict__ w_ih1, const float* __restrict__ w_hh1) {
    int idx = blockIdx.x * blockDim.x + threadIdx.x;   // 131072
    int t = idx & 255, k = idx >> 8;                   // k in 0..511
    const float* src = (k < 256) ? w_ih1 : w_hh1;
    int kk = k & 255;
    __half2 a = __floats2half2_rn(src[t * 256 + kk],         src[(t + 256) * 256 + kk]);
    __half2 b = __floats2half2_rn(src[(t + 512) * 256 + kk], src[(t + 768) * 256 + kk]);
    g_w1h[k * 256 + t] = make_uint2(*reinterpret_cast<uint*>(&a),
                                    *reinterpret_cast<uint*>(&b));
}

__global__ void tr_wo(const float* __restrict__ w_out) {
    int idx = blockIdx.x * blockDim.x + threadIdx.x;   // 16384
    int o = idx & 63, k = idx >> 6;
    g_woth[idx] = __float2half_rn(w_out[o * 256 + k]);
}

// per-batch-row init: gx0, h0/c0 for both layers (exact fp32)
__global__ void prep_init(const float* __restrict__ latent,
                          const float* __restrict__ w_lh, const float* __restrict__ b_lh,
                          const float* __restrict__ w_lc, const float* __restrict__ b_lc,
                          const float* __restrict__ w_ih0, const float* __restrict__ b_ih0,
                          const float* __restrict__ b_hh0) {
    __shared__ float lat[LATD];
    const int b = blockIdx.x, t = threadIdx.x;
    if (t < LATD) lat[t] = latent[b * LATD + t];
    __syncthreads();

    #pragma unroll
    for (int g = 0; g < 4; g++) {
        int n = t + 256 * g;
        const float4* wr = (const float4*)(w_ih0 + n * LATD);
        float acc = b_ih0[n] + b_hh0[n];
        #pragma unroll 8
        for (int q = 0; q < LATD / 4; q++) {
            float4 w4 = __ldg(wr + q);
            acc += lat[4 * q] * w4.x + lat[4 * q + 1] * w4.y +
                   lat[4 * q + 2] * w4.z + lat[4 * q + 3] * w4.w;
        }
        g_gx0[b * 1024 + n] = acc;
    }
    #pragma unroll
    for (int half = 0; half < 2; half++) {
        int j2 = t + 256 * half;
        {
            const float4* wr = (const float4*)(w_lh + j2 * LATD);
            float acc = b_lh[j2];
            #pragma unroll 8
            for (int q = 0; q < LATD / 4; q++) {
                float4 w4 = __ldg(wr + q);
                acc += lat[4 * q] * w4.x + lat[4 * q + 1] * w4.y +
                       lat[4 * q + 2] * w4.z + lat[4 * q + 3] * w4.w;
            }
            g_hinit[b * 512 + j2] = acc;
        }
        {
            const float4* wr = (const float4*)(w_lc + j2 * LATD);
            float acc = b_lc[j2];
            #pragma unroll 8
            for (int q = 0; q < LATD / 4; q++) {
                float4 w4 = __ldg(wr + q);
                acc += lat[4 * q] * w4.x + lat[4 * q + 1] * w4.y +
                       lat[4 * q + 2] * w4.z + lat[4 * q + 3] * w4.w;
            }
            g_cinit[b * 512 + j2] = acc;
        }
    }
}

// ================= main persistent kernel =================
// 128 CTAs x 256 threads. CTA owns 8 batch rows, packed as pairs (bp, bp+4).
// Thread t owns hidden unit j=t of both layers (gate rows t, t+256, t+512, t+768).
__global__ void __launch_bounds__(256, 1)
lstm_main(const float* __restrict__ b_ih1, const float* __restrict__ b_hh1,
          const float* __restrict__ b_out, float* __restrict__ out) {
    __shared__ ull xp[2][512][4];
    const int t  = threadIdx.x;
    const int bg = blockIdx.x * BC;

    ull c0p[4], c1p[4], gxp[4][4], b1p[4];
    #pragma unroll
    for (int bp = 0; bp < 4; bp++) {
        int b0 = bg + bp, b1 = bg + bp + 4;
        xp[0][t][bp]       = pk2(g_hinit[b0 * 512 + t],       g_hinit[b1 * 512 + t]);
        xp[0][256 + t][bp] = pk2(g_hinit[b0 * 512 + 256 + t], g_hinit[b1 * 512 + 256 + t]);
        c0p[bp] = pk2(g_cinit[b0 * 512 + t],       g_cinit[b1 * 512 + t]);
        c1p[bp] = pk2(g_cinit[b0 * 512 + 256 + t], g_cinit[b1 * 512 + 256 + t]);
        #pragma unroll
        for (int g = 0; g < 4; g++)
            gxp[g][bp] = pk2(g_gx0[b0 * 1024 + t + 256 * g],
                             g_gx0[b1 * 1024 + t + 256 * g]);
    }
    #pragma unroll
    for (int g = 0; g < 4; g++)
        b1p[g] = dup2f(b_ih1[t + 256 * g] + b_hh1[t + 256 * g]);

    const int oo = t & 63;
    const int rr = t >> 6;
    const ull bop = dup2f(b_out[oo]);

    __syncthreads();

    int cur = 0;
    for (int step = 0; step < T_STEPS; step++) {
        const int nxt = cur ^ 1;

        // ---------- layer 0: gates = gx0 + h0 @ Whh0^T ----------
        ull acc[4][4];
        #pragma unroll
        for (int g = 0; g < 4; g++)
            #pragma unroll
            for (int bp = 0; bp < 4; bp++) acc[g][bp] = gxp[g][bp];

        #pragma unroll 8
        for (int k = 0; k < 256; k++) {
            uint2 wp = __ldg(&g_w0h[k * 256 + t]);
            ull wx, wy, wz, ww; wexp(wp, wx, wy, wz, ww);
            ulonglong2 x01 = *reinterpret_cast<const ulonglong2*>(&xp[cur][k][0]);
            ulonglong2 x23 = *reinterpret_cast<const ulonglong2*>(&xp[cur][k][2]);
            ull xv[4] = {x01.x, x01.y, x23.x, x23.y};
            #pragma unroll
            for (int bp = 0; bp < 4; bp++) {
                acc[0][bp] = fma2(xv[bp], wx, acc[0][bp]);
                acc[1][bp] = fma2(xv[bp], wy, acc[1][bp]);
                acc[2][bp] = fma2(xv[bp], wz, acc[2][bp]);
                acc[3][bp] = fma2(xv[bp], ww, acc[3][bp]);
            }
        }
        #pragma unroll
        for (int bp = 0; bp < 4; bp++) {
            float ha, hb;
            lstm_cell(acc[0][bp], acc[1][bp], acc[2][bp], acc[3][bp], c0p[bp], ha, hb);
            xp[nxt][t][bp] = pk2(ha, hb);
        }
        __syncthreads();   // h0_new visible

        // ---------- layer 1: gates = bias1 + h0_new @ Wih1^T + h1 @ Whh1^T ----------
        #pragma unroll
        for (int g = 0; g < 4; g++)
            #pragma unroll
            for (int bp = 0; bp < 4; bp++) acc[g][bp] = b1p[g];

        #pragma unroll 8
        for (int k = 0; k < 256; k++) {
            uint2 wp = __ldg(&g_w1h[k * 256 + t]);
            ull wx, wy, wz, ww; wexp(wp, wx, wy, wz, ww);
            ulonglong2 x01 = *reinterpret_cast<const ulonglong2*>(&xp[nxt][k][0]);
            ulonglong2 x23 = *reinterpret_cast<const ulonglong2*>(&xp[nxt][k][2]);
            ull xv[4] = {x01.x, x01.y, x23.x, x23.y};
            #pragma unroll
            for (int bp = 0; bp < 4; bp++) {
                acc[0][bp] = fma2(xv[bp], wx, acc[0][bp]);
                acc[1][bp] = fma2(xv[bp], wy, acc[1][bp]);
                acc[2][bp] = fma2(xv[bp], wz, acc[2][bp]);
                acc[3][bp] = fma2(xv[bp], ww, acc[3][bp]);
            }
        }
        #pragma unroll 8
        for (int k = 0; k < 256; k++) {
            uint2 wp = __ldg(&g_w1h[(256 + k) * 256 + t]);
            ull wx, wy, wz, ww; wexp(wp, wx, wy, wz, ww);
            ulonglong2 x01 = *reinterpret_cast<const ulonglong2*>(&xp[cur][256 + k][0]);
            ulonglong2 x23 = *reinterpret_cast<const ulonglong2*>(&xp[cur][256 + k][2]);
            ull xv[4] = {x01.x, x01.y, x23.x, x23.y};
            #pragma unroll
            for (int bp = 0; bp < 4; bp++) {
                acc[0][bp] = fma2(xv[bp], wx, acc[0][bp]);
                acc[1][bp] = fma2(xv[bp], wy, acc[1][bp]);
                acc[2][bp] = fma2(xv[bp], wz, acc[2][bp]);
                acc[3][bp] = fma2(xv[bp], ww, acc[3][bp]);
            }
        }
        #pragma unroll
        for (int bp = 0; bp < 4; bp++) {
            float ha, hb;
            lstm_cell(acc[0][bp], acc[1][bp], acc[2][bp], acc[3][bp], c1p[bp], ha, hb);
            xp[nxt][256 + t][bp] = pk2(ha, hb);
        }
        __syncthreads();   // h1_new visible

        // ---------- output projection: out = h1_new @ Wout^T + b_out ----------
        ull oacc = bop;
        #pragma unroll 8
        for (int k = 0; k < 256; k++) {
            float wv = __half2float(__ldg(&g_woth[k * 64 + oo]));
            oacc = fma2(xp[nxt][256 + k][rr], dup2f(wv), oacc);
        }
        float va, vb;
        upk2(oacc, va, vb);
        out[((bg + rr) * T_STEPS + step) * OUTD + oo]     = va;
        out[((bg + rr + 4) * T_STEPS + step) * OUTD + oo] = vb;

        cur = nxt;
    }
}

// ================= launch =================
extern "C" void kernel_launch(void* const* d_in, const int* in_sizes, int n_in,
                              void* d_out, int out_size) {
    const float* latent = (const float*)d_in[0];
    const float* w_lh   = (const float*)d_in[1];
    const float* b_lh   = (const float*)d_in[2];
    const float* w_lc   = (const float*)d_in[3];
    const float* b_lc   = (const float*)d_in[4];
    const float* w_ih0  = (const float*)d_in[5];
    const float* w_hh0  = (const float*)d_in[6];
    const float* b_ih0  = (const float*)d_in[7];
    const float* b_hh0  = (const float*)d_in[8];
    const float* w_ih1  = (const float*)d_in[9];
    const float* w_hh1  = (const float*)d_in[10];
    const float* b_ih1  = (const float*)d_in[11];
    const float* b_hh1  = (const float*)d_in[12];
    const float* w_out  = (const float*)d_in[13];
    const float* b_out  = (const float*)d_in[14];
    float* out = (float*)d_out;

    tr_w0<<<256, 256>>>(w_hh0);
    tr_w1<<<512, 256>>>(w_ih1, w_hh1);
    tr_wo<<<64, 256>>>(w_out);
    prep_init<<<BATCH, 256>>>(latent, w_lh, b_lh, w_lc, b_lc, w_ih0, b_ih0, b_hh0);
    lstm_main<<<NCTA, 256>>>(b_ih1, b_hh1, b_out, out);
}

// round 12
// speedup vs baseline: 1.4605x; 1.4605x over previous
#include <cuda_runtime.h>
#include <cuda_bf16.h>
#include <cstdint>

#define TT    256
#define BATCH 1024
#define LATD  128
#define OUTD  64
#define HB    (BATCH * 256)

// SMEM layout (bytes)
#define SM_WFHI 0          // 98304: B-fragments hi, [6 chunks][64 slots][32 lanes] uint2
#define SM_WFLO 98304      // 98304: B-fragments lo
#define SM_AT   196608     // 34816: A tile 128 rows x 128 bf16, row stride 272B
#define SMEM_SZ 231424

// ---------------- static device scratch (no allocations) ----------------
__device__ uint32_t g_wfhi[393216], g_wflo[393216];  // [ntile][6][64][32][2] uint32
__device__ float g_wotp[256 * 64];                   // [unit][out]
__device__ float g_b1p[1024];                        // permuted bias1
__device__ float g_gx0p[BATCH * 1024];               // [b][permuted col]
__device__ float g_cinit[BATCH * 512];               // [b][layer*256+unit]
__device__ __nv_bfloat16 g_h0hi[2 * HB], g_h0lo[2 * HB];
__device__ __nv_bfloat16 g_h1hi[2 * HB], g_h1lo[2 * HB];
__device__ float g_opart[16 * 1024 * 64];            // [ntile][row][out]
__device__ unsigned g_bar;

// ---------------- helpers ----------------
__device__ __forceinline__ uint32_t s2u(const void* p) {
    uint32_t a;
    asm("{ .reg .u64 t; cvta.to.shared.u64 t, %1; cvt.u32.u64 %0, t; }" : "=r"(a) : "l"(p));
    return a;
}
__device__ __forceinline__ uint4 ldcg4(const void* p) {
    uint4 v;
    asm volatile("ld.global.cg.v4.u32 {%0,%1,%2,%3}, [%4];"
                 : "=r"(v.x), "=r"(v.y), "=r"(v.z), "=r"(v.w) : "l"(p));
    return v;
}
__device__ __forceinline__ void stcg4(void* p, uint4 v) {
    asm volatile("st.global.cg.v4.u32 [%0], {%1,%2,%3,%4};"
                 :: "l"(p), "r"(v.x), "r"(v.y), "r"(v.z), "r"(v.w) : "memory");
}
__device__ __forceinline__ void stg16(__nv_bfloat16* p, __nv_bfloat16 v) {
    unsigned short u = *(unsigned short*)&v;
    asm volatile("st.global.cg.u16 [%0], %1;" :: "l"(p), "h"(u) : "memory");
}
__device__ __forceinline__ float sigf(float x) { return __fdividef(1.f, 1.f + __expf(-x)); }
__device__ __forceinline__ float tanhf_(float x) {
    x = fminf(fmaxf(x, -15.f), 15.f);
    float e = __expf(2.f * x);
    return __fdividef(e - 1.f, e + 1.f);
}
// permuted column -> original gate row. col c of a CTA: gate=(c>>5)*2+(c&1),
// unit_local = ((c>>3)&3)*4 + ((c>>1)&3)
__device__ __forceinline__ int col2row(int ntile, int c) {
    int g = (c >> 5) * 2 + (c & 1);
    int u = ((c >> 3) & 3) * 4 + ((c >> 1) & 3);
    return g * 256 + ntile * 16 + u;
}

// ================= prep kernels =================
// B fragments in exact mma.sync n8k16 per-lane layout: lane holds b[k,n],
// n = nt*8 + (lane>>2), k = (lane&3)*2 + j + e*8.
__global__ void prep_wfrag(const float* __restrict__ w_hh0,
                           const float* __restrict__ w_ih1,
                           const float* __restrict__ w_hh1) {
    int gid = blockIdx.x * 256 + threadIdx.x;        // 393216
    int ntile = gid / 24576;
    int rem   = gid % 24576;
    int chunk = rem >> 12;                           // 0,1:L0  2..5:L1
    int r2    = rem & 4095;
    int ks    = r2 >> 9;
    int nt    = (r2 >> 6) & 7;
    int lane  = (r2 >> 1) & 31;
    int e     = r2 & 1;
    int c     = nt * 8 + (lane >> 2);
    int srow  = col2row(ntile, c);
    int kb    = (chunk < 2) ? chunk * 128 : (chunk - 2) * 128;
    uint32_t hi = 0, lo = 0;
    #pragma unroll
    for (int j = 0; j < 2; j++) {
        int kg = kb + ks * 16 + (lane & 3) * 2 + j + e * 8;
        float v;
        if (chunk < 2) v = w_hh0[srow * 256 + kg];
        else v = (kg < 256) ? w_ih1[srow * 256 + kg] : w_hh1[srow * 256 + kg - 256];
        __nv_bfloat16 h = __float2bfloat16(v);
        __nv_bfloat16 l = __float2bfloat16(v - __bfloat162float(h));
        hi |= (uint32_t)(*(uint16_t*)&h) << (16 * j);
        lo |= (uint32_t)(*(uint16_t*)&l) << (16 * j);
    }
    g_wfhi[gid] = hi;
    g_wflo[gid] = lo;
}

__global__ void prep_misc(const float* __restrict__ w_out,
                          const float* __restrict__ b_ih1,
                          const float* __restrict__ b_hh1) {
    int idx = blockIdx.x * 256 + threadIdx.x;        // 16384
    int o = idx & 63, u = idx >> 6;
    g_wotp[u * 64 + o] = w_out[o * 256 + u];
    if (idx < 1024) {
        int ntile = idx >> 6, c = idx & 63;
        int srow = col2row(ntile, c);
        g_b1p[idx] = b_ih1[srow] + b_hh1[srow];
    }
    if (idx == 0) g_bar = 0;
}

__global__ void prep_init(const float* __restrict__ latent,
                          const float* __restrict__ w_lh, const float* __restrict__ b_lh,
                          const float* __restrict__ w_lc, const float* __restrict__ b_lc,
                          const float* __restrict__ w_ih0, const float* __restrict__ b_ih0,
                          const float* __restrict__ b_hh0) {
    __shared__ float lat[LATD];
    const int b = blockIdx.x, t = threadIdx.x;
    if (t < LATD) lat[t] = latent[b * LATD + t];
    __syncthreads();

    #pragma unroll
    for (int g = 0; g < 4; g++) {
        int n = g * 256 + t;
        const float4* wr = (const float4*)(w_ih0 + n * LATD);
        float acc = b_ih0[n] + b_hh0[n];
        #pragma unroll 8
        for (int q = 0; q < LATD / 4; q++) {
            float4 w4 = __ldg(wr + q);
            acc += lat[4*q]*w4.x + lat[4*q+1]*w4.y + lat[4*q+2]*w4.z + lat[4*q+3]*w4.w;
        }
        // permuted col: unit t, gate g
        int colp = (t >> 4) * 64 + (g >> 1) * 32 + ((t >> 2) & 3) * 8 + (t & 3) * 2 + (g & 1);
        g_gx0p[b * 1024 + colp] = acc;
    }
    #pragma unroll
    for (int half = 0; half < 2; half++) {
        float hv, cv;
        {
            const float4* wr = (const float4*)(w_lh + (half * 256 + t) * LATD);
            float acc = b_lh[half * 256 + t];
            #pragma unroll 8
            for (int q = 0; q < LATD / 4; q++) {
                float4 w4 = __ldg(wr + q);
                acc += lat[4*q]*w4.x + lat[4*q+1]*w4.y + lat[4*q+2]*w4.z + lat[4*q+3]*w4.w;
            }
            hv = acc;
        }
        {
            const float4* wr = (const float4*)(w_lc + (half * 256 + t) * LATD);
            float acc = b_lc[half * 256 + t];
            #pragma unroll 8
            for (int q = 0; q < LATD / 4; q++) {
                float4 w4 = __ldg(wr + q);
                acc += lat[4*q]*w4.x + lat[4*q+1]*w4.y + lat[4*q+2]*w4.z + lat[4*q+3]*w4.w;
            }
            cv = acc;
        }
        __nv_bfloat16 hi = __float2bfloat16(hv);
        __nv_bfloat16 lo = __float2bfloat16(hv - __bfloat162float(hi));
        int p = HB + b * 256 + t;                    // initial h -> buffer 1
        if (half == 0) { g_h0hi[p] = hi; g_h0lo[p] = lo; }
        else           { g_h1hi[p] = hi; g_h1lo[p] = lo; }
        g_cinit[b * 512 + half * 256 + t] = cv;
    }
}

// ================= main kernel pieces =================
__device__ __forceinline__ void gbar(int tid, unsigned target) {
    __threadfence();
    __syncthreads();
    if (tid == 0) {
        atomicAdd(&g_bar, 1u);
        unsigned v;
        do {
            asm volatile("ld.acquire.gpu.global.u32 %0, [%1];" : "=r"(v) : "l"(&g_bar) : "memory");
        } while (v < target);
    }
    __syncthreads();
}

// copy 128 rows x 128 bf16 chunk (cols kofs..kofs+127) into padded A tile.
// 2048 uint4 total = 128 rows x 16 segments of 16B.
__device__ __forceinline__ void fill_A(char* smem, const __nv_bfloat16* src, int kofs, int tid) {
    const uint4* s4 = (const uint4*)(src + kofs);    // row stride 512B = 32 uint4
    #pragma unroll
    for (int it = 0; it < 8; it++) {
        int i = tid + it * 256;
        int r = i >> 4, seg = i & 15;                // FIXED: 16 segs/row (was >>3, &7)
        uint4 v = ldcg4(s4 + r * 32 + seg);
        *(uint4*)(smem + SM_AT + r * 272 + seg * 16) = v;
    }
}

// one GEMM pass over a K=128 chunk: 8 k-steps x 8 n-tiles
__device__ __forceinline__ void gemm_pass(uint32_t at_warp, uint32_t wf, float acc[8][4], int lane) {
    #pragma unroll
    for (int ks = 0; ks < 8; ks++) {
        uint32_t a0, a1, a2, a3;
        uint32_t aaddr = at_warp + (lane & 15) * 272 + ks * 32 + (lane >> 4) * 16;
        asm volatile("ldmatrix.sync.aligned.m8n8.x4.shared.b16 {%0,%1,%2,%3}, [%4];"
                     : "=r"(a0), "=r"(a1), "=r"(a2), "=r"(a3) : "r"(aaddr));
        #pragma unroll
        for (int nt = 0; nt < 8; nt++) {
            uint32_t b0, b1;
            uint32_t baddr = wf + ((ks * 8 + nt) * 32 + lane) * 8;
            asm volatile("ld.shared.v2.u32 {%0,%1}, [%2];" : "=r"(b0), "=r"(b1) : "r"(baddr));
            asm volatile(
                "mma.sync.aligned.m16n8k16.row.col.f32.bf16.bf16.f32 "
                "{%0,%1,%2,%3}, {%4,%5,%6,%7}, {%8,%9}, {%0,%1,%2,%3};"
                : "+f"(acc[nt][0]), "+f"(acc[nt][1]), "+f"(acc[nt][2]), "+f"(acc[nt][3])
                : "r"(a0), "r"(a1), "r"(a2), "r"(a3), "r"(b0), "r"(b1));
        }
    }
}

// 3-term split over one chunk: fill hi-A -> (Whi, Wlo) passes; fill lo-A -> Whi pass
__device__ __forceinline__ void do_chunk(char* smem, uint32_t sbase, int chunk,
                                         const __nv_bfloat16* ahi, const __nv_bfloat16* alo,
                                         int kofs, float acc[8][4], int tid, int lane,
                                         uint32_t at_warp) {
    uint32_t wfh = sbase + SM_WFHI + chunk * 16384;
    uint32_t wfl = sbase + SM_WFLO + chunk * 16384;
    fill_A(smem, ahi, kofs, tid);
    __syncthreads();
    gemm_pass(at_warp, wfh, acc, lane);
    gemm_pass(at_warp, wfl, acc, lane);
    __syncthreads();
    fill_A(smem, alo, kofs, tid);
    __syncthreads();
    gemm_pass(at_warp, wfh, acc, lane);
    __syncthreads();
}

__device__ __forceinline__ void cell_pub(float acc[8][4], float* c, float* hn,
                                         __nv_bfloat16* ghi, __nv_bfloat16* glo,
                                         int rbase, int ntile, int lane) {
    #pragma unroll
    for (int nt_ = 0; nt_ < 4; nt_++) {
        #pragma unroll
        for (int rh = 0; rh < 2; rh++) {
            int i = nt_ * 2 + rh;
            float gi = acc[nt_][rh * 2],     gf = acc[nt_][rh * 2 + 1];
            float gg = acc[nt_ + 4][rh * 2], go = acc[nt_ + 4][rh * 2 + 1];
            float cn = sigf(gf) * c[i] + sigf(gi) * tanhf_(gg);
            c[i] = cn;
            float h = sigf(go) * tanhf_(cn);
            hn[i] = h;
            __nv_bfloat16 hi = __float2bfloat16(h);
            __nv_bfloat16 lo = __float2bfloat16(h - __bfloat162float(hi));
            int rowg = rbase + rh * 8;
            int ug = ntile * 16 + nt_ * 4 + (lane & 3);
            stg16(ghi + rowg * 256 + ug, hi);
            stg16(glo + rowg * 256 + ug, lo);
        }
    }
}

__global__ void __launch_bounds__(256, 1)
lstm_mma(const float* __restrict__ b_out, float* __restrict__ out) {
    extern __shared__ char smem[];
    const int tid = threadIdx.x, wid = tid >> 5, lane = tid & 31;
    const int mtile = blockIdx.x >> 4, ntile = blockIdx.x & 15;
    const uint32_t sbase = s2u(smem);
    const uint32_t at_warp = sbase + SM_AT + wid * 16 * 272;
    const int rbase = mtile * 128 + wid * 16 + (lane >> 2);
    const int hoff = mtile * 128 * 256;

    // weight fragments -> SMEM
    {
        const uint4* sh = (const uint4*)(g_wfhi + ntile * 24576);
        const uint4* sl = (const uint4*)(g_wflo + ntile * 24576);
        uint4* dh = (uint4*)(smem + SM_WFHI);
        uint4* dl = (uint4*)(smem + SM_WFLO);
        for (int i = tid; i < 6144; i += 256) { dh[i] = __ldg(sh + i); dl[i] = __ldg(sl + i); }
    }

    // per-lane constants
    float gx[8][4], b1r[8][2];
    #pragma unroll
    for (int nt = 0; nt < 8; nt++) {
        #pragma unroll
        for (int r = 0; r < 4; r++) {
            int rowg = rbase + (r >> 1) * 8;
            int c = nt * 8 + 2 * (lane & 3) + (r & 1);
            gx[nt][r] = __ldg(&g_gx0p[rowg * 1024 + ntile * 64 + c]);
        }
        b1r[nt][0] = __ldg(&g_b1p[ntile * 64 + nt * 8 + 2 * (lane & 3)]);
        b1r[nt][1] = __ldg(&g_b1p[ntile * 64 + nt * 8 + 2 * (lane & 3) + 1]);
    }
    float c0[8], c1[8];
    #pragma unroll
    for (int i = 0; i < 8; i++) {
        int rowg = rbase + (i & 1) * 8;
        int ug = ntile * 16 + (i >> 1) * 4 + (lane & 3);
        c0[i] = __ldg(&g_cinit[rowg * 512 + ug]);
        c1[i] = __ldg(&g_cinit[rowg * 512 + 256 + ug]);
    }
    __syncthreads();

    unsigned tgt = 128;
    float acc[8][4];

    #pragma unroll 1
    for (int s = 0; s < TT; s++) {
        // out reduction for step s-1 (partials stable after barrier B(s-1))
        if (s > 0 && tid < 128) {
            int rowg = mtile * 128 + tid;
            float4 a = __ldg((const float4*)(b_out + ntile * 4));
            #pragma unroll
            for (int nt = 0; nt < 16; nt++) {
                uint4 v = ldcg4(&g_opart[(nt * 1024 + rowg) * 64 + ntile * 4]);
                a.x += __uint_as_float(v.x); a.y += __uint_as_float(v.y);
                a.z += __uint_as_float(v.z); a.w += __uint_as_float(v.w);
            }
            *(float4*)&out[(rowg * TT + s - 1) * OUTD + ntile * 4] = a;
        }
        const int wb = s & 1, rb = wb ^ 1;

        // ---------------- layer 0 ----------------
        #pragma unroll
        for (int nt = 0; nt < 8; nt++)
            #pragma unroll
            for (int r = 0; r < 4; r++) acc[nt][r] = gx[nt][r];
        do_chunk(smem, sbase, 0, g_h0hi + rb * HB + hoff, g_h0lo + rb * HB + hoff, 0,   acc, tid, lane, at_warp);
        do_chunk(smem, sbase, 1, g_h0hi + rb * HB + hoff, g_h0lo + rb * HB + hoff, 128, acc, tid, lane, at_warp);

        float h0n[8];
        cell_pub(acc, c0, h0n, g_h0hi + wb * HB, g_h0lo + wb * HB, rbase, ntile, lane);
        gbar(tid, tgt); tgt += 128;                  // barrier A: h0_new visible

        // ---------------- layer 1 ----------------
        #pragma unroll
        for (int nt = 0; nt < 8; nt++) {
            acc[nt][0] = b1r[nt][0]; acc[nt][1] = b1r[nt][1];
            acc[nt][2] = b1r[nt][0]; acc[nt][3] = b1r[nt][1];
        }
        do_chunk(smem, sbase, 2, g_h0hi + wb * HB + hoff, g_h0lo + wb * HB + hoff, 0,   acc, tid, lane, at_warp);
        do_chunk(smem, sbase, 3, g_h0hi + wb * HB + hoff, g_h0lo + wb * HB + hoff, 128, acc, tid, lane, at_warp);
        do_chunk(smem, sbase, 4, g_h1hi + rb * HB + hoff, g_h1lo + rb * HB + hoff, 0,   acc, tid, lane, at_warp);
        do_chunk(smem, sbase, 5, g_h1hi + rb * HB + hoff, g_h1lo + rb * HB + hoff, 128, acc, tid, lane, at_warp);

        float h1n[8];
        cell_pub(acc, c1, h1n, g_h1hi + wb * HB, g_h1lo + wb * HB, rbase, ntile, lane);

        // out partials: lane (a = lane&3) computes outs [a*16, a*16+16) for its 2 rows
        {
            float po0[16], po1[16];
            #pragma unroll
            for (int o = 0; o < 16; o++) { po0[o] = 0.f; po1[o] = 0.f; }
            #pragma unroll
            for (int uu = 0; uu < 16; uu++) {
                float hv0 = __shfl_sync(0xffffffffu, h1n[(uu >> 2) * 2],     uu & 3, 4);
                float hv1 = __shfl_sync(0xffffffffu, h1n[(uu >> 2) * 2 + 1], uu & 3, 4);
                const float4* wr = (const float4*)(g_wotp + (ntile * 16 + uu) * 64 + (lane & 3) * 16);
                #pragma unroll
                for (int q = 0; q < 4; q++) {
                    float4 w = __ldg(wr + q);
                    po0[q*4+0] += hv0 * w.x; po0[q*4+1] += hv0 * w.y;
                    po0[q*4+2] += hv0 * w.z; po0[q*4+3] += hv0 * w.w;
                    po1[q*4+0] += hv1 * w.x; po1[q*4+1] += hv1 * w.y;
                    po1[q*4+2] += hv1 * w.z; po1[q*4+3] += hv1 * w.w;
                }
            }
            float* p0 = &g_opart[(ntile * 1024 + rbase) * 64 + (lane & 3) * 16];
            float* p1 = &g_opart[(ntile * 1024 + rbase + 8) * 64 + (lane & 3) * 16];
            #pragma unroll
            for (int q = 0; q < 4; q++) {
                stcg4(p0 + q * 4, make_uint4(__float_as_uint(po0[q*4]),   __float_as_uint(po0[q*4+1]),
                                             __float_as_uint(po0[q*4+2]), __float_as_uint(po0[q*4+3])));
                stcg4(p1 + q * 4, make_uint4(__float_as_uint(po1[q*4]),   __float_as_uint(po1[q*4+1]),
                                             __float_as_uint(po1[q*4+2]), __float_as_uint(po1[q*4+3])));
            }
        }
        gbar(tid, tgt); tgt += 128;                  // barrier B: h1_new + partials visible
    }

    // final out reduction (step TT-1)
    if (tid < 128) {
        int rowg = mtile * 128 + tid;
        float4 a = __ldg((const float4*)(b_out + ntile * 4));
        #pragma unroll
        for (int nt = 0; nt < 16; nt++) {
            uint4 v = ldcg4(&g_opart[(nt * 1024 + rowg) * 64 + ntile * 4]);
            a.x += __uint_as_float(v.x); a.y += __uint_as_float(v.y);
            a.z += __uint_as_float(v.z); a.w += __uint_as_float(v.w);
        }
        *(float4*)&out[(rowg * TT + TT - 1) * OUTD + ntile * 4] = a;
    }
}

// ================= launch =================
extern "C" void kernel_launch(void* const* d_in, const int* in_sizes, int n_in,
                              void* d_out, int out_size) {
    const float* latent = (const float*)d_in[0];
    const float* w_lh   = (const float*)d_in[1];
    const float* b_lh   = (const float*)d_in[2];
    const float* w_lc   = (const float*)d_in[3];
    const float* b_lc   = (const float*)d_in[4];
    const float* w_ih0  = (const float*)d_in[5];
    const float* w_hh0  = (const float*)d_in[6];
    const float* b_ih0  = (const float*)d_in[7];
    const float* b_hh0  = (const float*)d_in[8];
    const float* w_ih1  = (const float*)d_in[9];
    const float* w_hh1  = (const float*)d_in[10];
    const float* b_ih1  = (const float*)d_in[11];
    const float* b_hh1  = (const float*)d_in[12];
    const float* w_out  = (const float*)d_in[13];
    const float* b_out  = (const float*)d_in[14];
    float* out = (float*)d_out;

    cudaFuncSetAttribute(lstm_mma, cudaFuncAttributeMaxDynamicSharedMemorySize, SMEM_SZ);

    prep_wfrag<<<1536, 256>>>(w_hh0, w_ih1, w_hh1);
    prep_misc<<<64, 256>>>(w_out, b_ih1, b_hh1);
    prep_init<<<BATCH, 256>>>(latent, w_lh, b_lh, w_lc, b_lc, w_ih0, b_ih0, b_hh0);
    lstm_mma<<<128, 256, SMEM_SZ>>>(b_out, out);
}

// round 13
// speedup vs baseline: 2.6012x; 1.7810x over previous
#include <cuda_runtime.h>
#include <cuda_fp16.h>
#include <cstdint>

#define TT    256
#define BATCH 1024
#define LATD  128
#define OUTD  64
#define HB    (BATCH * 256)

// SMEM layout (bytes)
#define SM_WF   0          // 98304: B-fragments fp16, [6 chunks][64 slots][32 lanes] uint2
#define SM_AT   98304      // 34816: A tile 128 rows x 128 fp16, row stride 272B
#define SMEM_SZ 133120

// ---------------- static device scratch (no allocations) ----------------
__device__ uint32_t g_wf[393216];                    // [ntile][6][64][32][2] uint32 (fp16x2)
__device__ float g_wotp[256 * 64];                   // [unit][out]
__device__ float g_b1p[1024];                        // permuted bias1
__device__ float g_gx0p[BATCH * 1024];               // [b][permuted col]
__device__ float g_cinit[BATCH * 512];               // [b][layer*256+unit]
__device__ __half g_h0f[2 * HB], g_h1f[2 * HB];      // double-buffered fp16 h
__device__ float g_opart[16 * 1024 * 64];            // [ntile][row][out]
__device__ unsigned g_bar;

// ---------------- helpers ----------------
__device__ __forceinline__ uint32_t s2u(const void* p) {
    uint32_t a;
    asm("{ .reg .u64 t; cvta.to.shared.u64 t, %1; cvt.u32.u64 %0, t; }" : "=r"(a) : "l"(p));
    return a;
}
__device__ __forceinline__ uint4 ldcg4(const void* p) {
    uint4 v;
    asm volatile("ld.global.cg.v4.u32 {%0,%1,%2,%3}, [%4];"
                 : "=r"(v.x), "=r"(v.y), "=r"(v.z), "=r"(v.w) : "l"(p));
    return v;
}
__device__ __forceinline__ void stcg4(void* p, uint4 v) {
    asm volatile("st.global.cg.v4.u32 [%0], {%1,%2,%3,%4};"
                 :: "l"(p), "r"(v.x), "r"(v.y), "r"(v.z), "r"(v.w) : "memory");
}
__device__ __forceinline__ void stg16(__half* p, __half v) {
    unsigned short u = *(unsigned short*)&v;
    asm volatile("st.global.cg.u16 [%0], %1;" :: "l"(p), "h"(u) : "memory");
}
__device__ __forceinline__ float sigf(float x) { return __fdividef(1.f, 1.f + __expf(-x)); }
__device__ __forceinline__ float tanhf_(float x) {
    x = fminf(fmaxf(x, -15.f), 15.f);
    float e = __expf(2.f * x);
    return __fdividef(e - 1.f, e + 1.f);
}
// permuted column -> original gate row. col c of a CTA: gate=(c>>5)*2+(c&1),
// unit_local = ((c>>3)&3)*4 + ((c>>1)&3)
__device__ __forceinline__ int col2row(int ntile, int c) {
    int g = (c >> 5) * 2 + (c & 1);
    int u = ((c >> 3) & 3) * 4 + ((c >> 1) & 3);
    return g * 256 + ntile * 16 + u;
}

// ================= prep kernels =================
// B fragments in exact mma.sync n8k16 per-lane layout: lane holds b[k,n],
// n = nt*8 + (lane>>2), k = (lane&3)*2 + j + e*8.
__global__ void prep_wfrag(const float* __restrict__ w_hh0,
                           const float* __restrict__ w_ih1,
                           const float* __restrict__ w_hh1) {
    int gid = blockIdx.x * 256 + threadIdx.x;        // 393216
    int ntile = gid / 24576;
    int rem   = gid % 24576;
    int chunk = rem >> 12;                           // 0,1:L0  2..5:L1
    int r2    = rem & 4095;
    int ks    = r2 >> 9;
    int nt    = (r2 >> 6) & 7;
    int lane  = (r2 >> 1) & 31;
    int e     = r2 & 1;
    int c     = nt * 8 + (lane >> 2);
    int srow  = col2row(ntile, c);
    int kb    = (chunk < 2) ? chunk * 128 : (chunk - 2) * 128;
    uint32_t w = 0;
    #pragma unroll
    for (int j = 0; j < 2; j++) {
        int kg = kb + ks * 16 + (lane & 3) * 2 + j + e * 8;
        float v;
        if (chunk < 2) v = w_hh0[srow * 256 + kg];
        else v = (kg < 256) ? w_ih1[srow * 256 + kg] : w_hh1[srow * 256 + kg - 256];
        __half h = __float2half_rn(v);
        w |= (uint32_t)(*(uint16_t*)&h) << (16 * j);
    }
    g_wf[gid] = w;
}

__global__ void prep_misc(const float* __restrict__ w_out,
                          const float* __restrict__ b_ih1,
                          const float* __restrict__ b_hh1) {
    int idx = blockIdx.x * 256 + threadIdx.x;        // 16384
    int o = idx & 63, u = idx >> 6;
    g_wotp[u * 64 + o] = w_out[o * 256 + u];
    if (idx < 1024) {
        int ntile = idx >> 6, c = idx & 63;
        int srow = col2row(ntile, c);
        g_b1p[idx] = b_ih1[srow] + b_hh1[srow];
    }
    if (idx == 0) g_bar = 0;
}

__global__ void prep_init(const float* __restrict__ latent,
                          const float* __restrict__ w_lh, const float* __restrict__ b_lh,
                          const float* __restrict__ w_lc, const float* __restrict__ b_lc,
                          const float* __restrict__ w_ih0, const float* __restrict__ b_ih0,
                          const float* __restrict__ b_hh0) {
    __shared__ float lat[LATD];
    const int b = blockIdx.x, t = threadIdx.x;
    if (t < LATD) lat[t] = latent[b * LATD + t];
    __syncthreads();

    #pragma unroll
    for (int g = 0; g < 4; g++) {
        int n = g * 256 + t;
        const float4* wr = (const float4*)(w_ih0 + n * LATD);
        float acc = b_ih0[n] + b_hh0[n];
        #pragma unroll 8
        for (int q = 0; q < LATD / 4; q++) {
            float4 w4 = __ldg(wr + q);
            acc += lat[4*q]*w4.x + lat[4*q+1]*w4.y + lat[4*q+2]*w4.z + lat[4*q+3]*w4.w;
        }
        // permuted col: unit t, gate g
        int colp = (t >> 4) * 64 + (g >> 1) * 32 + ((t >> 2) & 3) * 8 + (t & 3) * 2 + (g & 1);
        g_gx0p[b * 1024 + colp] = acc;
    }
    #pragma unroll
    for (int half = 0; half < 2; half++) {
        float hv, cv;
        {
            const float4* wr = (const float4*)(w_lh + (half * 256 + t) * LATD);
            float acc = b_lh[half * 256 + t];
            #pragma unroll 8
            for (int q = 0; q < LATD / 4; q++) {
                float4 w4 = __ldg(wr + q);
                acc += lat[4*q]*w4.x + lat[4*q+1]*w4.y + lat[4*q+2]*w4.z + lat[4*q+3]*w4.w;
            }
            hv = acc;
        }
        {
            const float4* wr = (const float4*)(w_lc + (half * 256 + t) * LATD);
            float acc = b_lc[half * 256 + t];
            #pragma unroll 8
            for (int q = 0; q < LATD / 4; q++) {
                float4 w4 = __ldg(wr + q);
                acc += lat[4*q]*w4.x + lat[4*q+1]*w4.y + lat[4*q+2]*w4.z + lat[4*q+3]*w4.w;
            }
            cv = acc;
        }
        int p = HB + b * 256 + t;                    // initial h -> buffer 1
        if (half == 0) g_h0f[p] = __float2half_rn(hv);
        else           g_h1f[p] = __float2half_rn(hv);
        g_cinit[b * 512 + half * 256 + t] = cv;
    }
}

// ================= main kernel pieces =================
__device__ __forceinline__ void gbar(int tid, unsigned target) {
    __threadfence();
    __syncthreads();
    if (tid == 0) {
        atomicAdd(&g_bar, 1u);
        unsigned v;
        do {
            asm volatile("ld.acquire.gpu.global.u32 %0, [%1];" : "=r"(v) : "l"(&g_bar) : "memory");
        } while (v < target);
    }
    __syncthreads();
}

// copy 128 rows x 128 fp16 chunk (cols kofs..kofs+127) into padded A tile.
// 2048 uint4 total = 128 rows x 16 segments of 16B.
__device__ __forceinline__ void fill_A(char* smem, const __half* src, int kofs, int tid) {
    const uint4* s4 = (const uint4*)(src + kofs);    // row stride 512B = 32 uint4
    #pragma unroll
    for (int it = 0; it < 8; it++) {
        int i = tid + it * 256;
        int r = i >> 4, seg = i & 15;
        uint4 v = ldcg4(s4 + r * 32 + seg);
        *(uint4*)(smem + SM_AT + r * 272 + seg * 16) = v;
    }
}

// one GEMM pass over a K=128 chunk: 8 k-steps x 8 n-tiles (fp16 single pass)
__device__ __forceinline__ void gemm_pass(uint32_t at_warp, uint32_t wf, float acc[8][4], int lane) {
    #pragma unroll
    for (int ks = 0; ks < 8; ks++) {
        uint32_t a0, a1, a2, a3;
        uint32_t aaddr = at_warp + (lane & 15) * 272 + ks * 32 + (lane >> 4) * 16;
        asm volatile("ldmatrix.sync.aligned.m8n8.x4.shared.b16 {%0,%1,%2,%3}, [%4];"
                     : "=r"(a0), "=r"(a1), "=r"(a2), "=r"(a3) : "r"(aaddr));
        #pragma unroll
        for (int nt = 0; nt < 8; nt++) {
            uint32_t b0, b1;
            uint32_t baddr = wf + ((ks * 8 + nt) * 32 + lane) * 8;
            asm volatile("ld.shared.v2.u32 {%0,%1}, [%2];" : "=r"(b0), "=r"(b1) : "r"(baddr));
            asm volatile(
                "mma.sync.aligned.m16n8k16.row.col.f32.f16.f16.f32 "
                "{%0,%1,%2,%3}, {%4,%5,%6,%7}, {%8,%9}, {%0,%1,%2,%3};"
                : "+f"(acc[nt][0]), "+f"(acc[nt][1]), "+f"(acc[nt][2]), "+f"(acc[nt][3])
                : "r"(a0), "r"(a1), "r"(a2), "r"(a3), "r"(b0), "r"(b1));
        }
    }
}

// one chunk: fill A, one fp16 pass
__device__ __forceinline__ void do_chunk(char* smem, uint32_t sbase, int chunk,
                                         const __half* a, int kofs, float acc[8][4],
                                         int tid, int lane, uint32_t at_warp) {
    uint32_t wf = sbase + SM_WF + chunk * 16384;
    fill_A(smem, a, kofs, tid);
    __syncthreads();
    gemm_pass(at_warp, wf, acc, lane);
    __syncthreads();
}

__device__ __forceinline__ void cell_pub(float acc[8][4], float* c, float* hn,
                                         __half* gh, int rbase, int ntile, int lane) {
    #pragma unroll
    for (int nt_ = 0; nt_ < 4; nt_++) {
        #pragma unroll
        for (int rh = 0; rh < 2; rh++) {
            int i = nt_ * 2 + rh;
            float gi = acc[nt_][rh * 2],     gf = acc[nt_][rh * 2 + 1];
            float gg = acc[nt_ + 4][rh * 2], go = acc[nt_ + 4][rh * 2 + 1];
            float cn = sigf(gf) * c[i] + sigf(gi) * tanhf_(gg);
            c[i] = cn;
            float h = sigf(go) * tanhf_(cn);
            hn[i] = h;
            int rowg = rbase + rh * 8;
            int ug = ntile * 16 + nt_ * 4 + (lane & 3);
            stg16(gh + rowg * 256 + ug, __float2half_rn(h));
        }
    }
}

__global__ void __launch_bounds__(256, 1)
lstm_mma(const float* __restrict__ b_out, float* __restrict__ out) {
    extern __shared__ char smem[];
    const int tid = threadIdx.x, wid = tid >> 5, lane = tid & 31;
    const int mtile = blockIdx.x >> 4, ntile = blockIdx.x & 15;
    const uint32_t sbase = s2u(smem);
    const uint32_t at_warp = sbase + SM_AT + wid * 16 * 272;
    const int rbase = mtile * 128 + wid * 16 + (lane >> 2);
    const int hoff = mtile * 128 * 256;

    // weight fragments -> SMEM
    {
        const uint4* sh = (const uint4*)(g_wf + ntile * 24576);
        uint4* dh = (uint4*)(smem + SM_WF);
        for (int i = tid; i < 6144; i += 256) dh[i] = __ldg(sh + i);
    }

    // per-lane constants
    float gx[8][4], b1r[8][2];
    #pragma unroll
    for (int nt = 0; nt < 8; nt++) {
        #pragma unroll
        for (int r = 0; r < 4; r++) {
            int rowg = rbase + (r >> 1) * 8;
            int c = nt * 8 + 2 * (lane & 3) + (r & 1);
            gx[nt][r] = __ldg(&g_gx0p[rowg * 1024 + ntile * 64 + c]);
        }
        b1r[nt][0] = __ldg(&g_b1p[ntile * 64 + nt * 8 + 2 * (lane & 3)]);
        b1r[nt][1] = __ldg(&g_b1p[ntile * 64 + nt * 8 + 2 * (lane & 3) + 1]);
    }
    float c0[8], c1[8];
    #pragma unroll
    for (int i = 0; i < 8; i++) {
        int rowg = rbase + (i & 1) * 8;
        int ug = ntile * 16 + (i >> 1) * 4 + (lane & 3);
        c0[i] = __ldg(&g_cinit[rowg * 512 + ug]);
        c1[i] = __ldg(&g_cinit[rowg * 512 + 256 + ug]);
    }
    __syncthreads();

    unsigned tgt = 128;
    float acc[8][4];

    #pragma unroll 1
    for (int s = 0; s < TT; s++) {
        // out reduction for step s-1 (partials stable after barrier B(s-1))
        if (s > 0 && tid < 128) {
            int rowg = mtile * 128 + tid;
            float4 a = __ldg((const float4*)(b_out + ntile * 4));
            #pragma unroll
            for (int nt = 0; nt < 16; nt++) {
                uint4 v = ldcg4(&g_opart[(nt * 1024 + rowg) * 64 + ntile * 4]);
                a.x += __uint_as_float(v.x); a.y += __uint_as_float(v.y);
                a.z += __uint_as_float(v.z); a.w += __uint_as_float(v.w);
            }
            *(float4*)&out[(rowg * TT + s - 1) * OUTD + ntile * 4] = a;
        }
        const int wb = s & 1, rb = wb ^ 1;

        // ---------------- layer 0 ----------------
        #pragma unroll
        for (int nt = 0; nt < 8; nt++)
            #pragma unroll
            for (int r = 0; r < 4; r++) acc[nt][r] = gx[nt][r];
        do_chunk(smem, sbase, 0, g_h0f + rb * HB + hoff, 0,   acc, tid, lane, at_warp);
        do_chunk(smem, sbase, 1, g_h0f + rb * HB + hoff, 128, acc, tid, lane, at_warp);

        float h0n[8];
        cell_pub(acc, c0, h0n, g_h0f + wb * HB, rbase, ntile, lane);
        gbar(tid, tgt); tgt += 128;                  // barrier A: h0_new visible

        // ---------------- layer 1 ----------------
        #pragma unroll
        for (int nt = 0; nt < 8; nt++) {
            acc[nt][0] = b1r[nt][0]; acc[nt][1] = b1r[nt][1];
            acc[nt][2] = b1r[nt][0]; acc[nt][3] = b1r[nt][1];
        }
        do_chunk(smem, sbase, 2, g_h0f + wb * HB + hoff, 0,   acc, tid, lane, at_warp);
        do_chunk(smem, sbase, 3, g_h0f + wb * HB + hoff, 128, acc, tid, lane, at_warp);
        do_chunk(smem, sbase, 4, g_h1f + rb * HB + hoff, 0,   acc, tid, lane, at_warp);
        do_chunk(smem, sbase, 5, g_h1f + rb * HB + hoff, 128, acc, tid, lane, at_warp);

        float h1n[8];
        cell_pub(acc, c1, h1n, g_h1f + wb * HB, rbase, ntile, lane);

        // out partials: lane (a = lane&3) computes outs [a*16, a*16+16) for its 2 rows
        {
            float po0[16], po1[16];
            #pragma unroll
            for (int o = 0; o < 16; o++) { po0[o] = 0.f; po1[o] = 0.f; }
            #pragma unroll
            for (int uu = 0; uu < 16; uu++) {
                float hv0 = __shfl_sync(0xffffffffu, h1n[(uu >> 2) * 2],     uu & 3, 4);
                float hv1 = __shfl_sync(0xffffffffu, h1n[(uu >> 2) * 2 + 1], uu & 3, 4);
                const float4* wr = (const float4*)(g_wotp + (ntile * 16 + uu) * 64 + (lane & 3) * 16);
                #pragma unroll
                for (int q = 0; q < 4; q++) {
                    float4 w = __ldg(wr + q);
                    po0[q*4+0] += hv0 * w.x; po0[q*4+1] += hv0 * w.y;
                    po0[q*4+2] += hv0 * w.z; po0[q*4+3] += hv0 * w.w;
                    po1[q*4+0] += hv1 * w.x; po1[q*4+1] += hv1 * w.y;
                    po1[q*4+2] += hv1 * w.z; po1[q*4+3] += hv1 * w.w;
                }
            }
            float* p0 = &g_opart[(ntile * 1024 + rbase) * 64 + (lane & 3) * 16];
            float* p1 = &g_opart[(ntile * 1024 + rbase + 8) * 64 + (lane & 3) * 16];
            #pragma unroll
            for (int q = 0; q < 4; q++) {
                stcg4(p0 + q * 4, make_uint4(__float_as_uint(po0[q*4]),   __float_as_uint(po0[q*4+1]),
                                             __float_as_uint(po0[q*4+2]), __float_as_uint(po0[q*4+3])));
                stcg4(p1 + q * 4, make_uint4(__float_as_uint(po1[q*4]),   __float_as_uint(po1[q*4+1]),
                                             __float_as_uint(po1[q*4+2]), __float_as_uint(po1[q*4+3])));
            }
        }
        gbar(tid, tgt); tgt += 128;                  // barrier B: h1_new + partials visible
    }

    // final out reduction (step TT-1)
    if (tid < 128) {
        int rowg = mtile * 128 + tid;
        float4 a = __ldg((const float4*)(b_out + ntile * 4));
        #pragma unroll
        for (int nt = 0; nt < 16; nt++) {
            uint4 v = ldcg4(&g_opart[(nt * 1024 + rowg) * 64 + ntile * 4]);
            a.x += __uint_as_float(v.x); a.y += __uint_as_float(v.y);
            a.z += __uint_as_float(v.z); a.w += __uint_as_float(v.w);
        }
        *(float4*)&out[(rowg * TT + TT - 1) * OUTD + ntile * 4] = a;
    }
}

// ================= launch =================
extern "C" void kernel_launch(void* const* d_in, const int* in_sizes, int n_in,
                              void* d_out, int out_size) {
    const float* latent = (const float*)d_in[0];
    const float* w_lh   = (const float*)d_in[1];
    const float* b_lh   = (const float*)d_in[2];
    const float* w_lc   = (const float*)d_in[3];
    const float* b_lc   = (const float*)d_in[4];
    const float* w_ih0  = (const float*)d_in[5];
    const float* w_hh0  = (const float*)d_in[6];
    const float* b_ih0  = (const float*)d_in[7];
    const float* b_hh0  = (const float*)d_in[8];
    const float* w_ih1  = (const float*)d_in[9];
    const float* w_hh1  = (const float*)d_in[10];
    const float* b_ih1  = (const float*)d_in[11];
    const float* b_hh1  = (const float*)d_in[12];
    const float* w_out  = (const float*)d_in[13];
    const float* b_out  = (const float*)d_in[14];
    float* out = (float*)d_out;

    cudaFuncSetAttribute(lstm_mma, cudaFuncAttributeMaxDynamicSharedMemorySize, SMEM_SZ);

    prep_wfrag<<<1536, 256>>>(w_hh0, w_ih1, w_hh1);
    prep_misc<<<64, 256>>>(w_out, b_ih1, b_hh1);
    prep_init<<<BATCH, 256>>>(latent, w_lh, b_lh, w_lc, b_lc, w_ih0, b_ih0, b_hh0);
    lstm_mma<<<128, 256, SMEM_SZ>>>(b_out, out);
}

// round 14
// speedup vs baseline: 2.7176x; 1.0448x over previous
#include <cuda_runtime.h>
#include <cuda_fp16.h>
#include <cstdint>

#define TT    256
#define BATCH 1024
#define LATD  128
#define OUTD  64
#define HB    (BATCH * 256)

// SMEM layout (bytes)
#define SM_WF   0          // 98304: B-fragments fp16, [6 chunks][64 slots][32 lanes] uint2
#define SM_AT0  98304      // 34816: A tile buf0, 128 rows x 128 fp16, row stride 272B
#define SM_AT1  133120     // 34816: A tile buf1
#define SMEM_SZ 167936

// ---------------- static device scratch (no allocations) ----------------
__device__ uint32_t g_wf[393216];                    // [ntile][6][64][32][2] uint32 (fp16x2)
__device__ float g_wotp[256 * 64];                   // [unit][out]
__device__ float g_b1p[1024];                        // permuted bias1
__device__ float g_gx0p[BATCH * 1024];               // [b][permuted col]
__device__ float g_cinit[BATCH * 512];               // [b][layer*256+unit]
__device__ __half g_h0f[2 * HB], g_h1f[2 * HB];      // double-buffered fp16 h
__device__ float g_opart[16 * 1024 * 64];            // [ntile][row][out]
__device__ unsigned g_barm[8];                       // per-mtile barrier counters

// ---------------- helpers ----------------
__device__ __forceinline__ uint32_t s2u(const void* p) {
    uint32_t a;
    asm("{ .reg .u64 t; cvta.to.shared.u64 t, %1; cvt.u32.u64 %0, t; }" : "=r"(a) : "l"(p));
    return a;
}
__device__ __forceinline__ uint4 ldcg4(const void* p) {
    uint4 v;
    asm volatile("ld.global.cg.v4.u32 {%0,%1,%2,%3}, [%4];"
                 : "=r"(v.x), "=r"(v.y), "=r"(v.z), "=r"(v.w) : "l"(p));
    return v;
}
__device__ __forceinline__ void stcg4(void* p, uint4 v) {
    asm volatile("st.global.cg.v4.u32 [%0], {%1,%2,%3,%4};"
                 :: "l"(p), "r"(v.x), "r"(v.y), "r"(v.z), "r"(v.w) : "memory");
}
__device__ __forceinline__ void stg16(__half* p, __half v) {
    unsigned short u = *(unsigned short*)&v;
    asm volatile("st.global.cg.u16 [%0], %1;" :: "l"(p), "h"(u) : "memory");
}
__device__ __forceinline__ void cpa16(uint32_t saddr, const void* gptr) {
    asm volatile("cp.async.cg.shared.global [%0], [%1], 16;" :: "r"(saddr), "l"(gptr) : "memory");
}
#define CP_COMMIT() asm volatile("cp.async.commit_group;" ::: "memory")
#define CP_WAIT0()  asm volatile("cp.async.wait_group 0;" ::: "memory")

__device__ __forceinline__ float sigf(float x) { return __fdividef(1.f, 1.f + __expf(-x)); }
__device__ __forceinline__ float tanhf_(float x) {
    x = fminf(fmaxf(x, -15.f), 15.f);
    float e = __expf(2.f * x);
    return __fdividef(e - 1.f, e + 1.f);
}
// permuted column -> original gate row. col c of a CTA: gate=(c>>5)*2+(c&1),
// unit_local = ((c>>3)&3)*4 + ((c>>1)&3)
__device__ __forceinline__ int col2row(int ntile, int c) {
    int g = (c >> 5) * 2 + (c & 1);
    int u = ((c >> 3) & 3) * 4 + ((c >> 1) & 3);
    return g * 256 + ntile * 16 + u;
}

// ================= prep kernels =================
// B fragments in exact mma.sync n8k16 per-lane layout: lane holds b[k,n],
// n = nt*8 + (lane>>2), k = (lane&3)*2 + j + e*8.
__global__ void prep_wfrag(const float* __restrict__ w_hh0,
                           const float* __restrict__ w_ih1,
                           const float* __restrict__ w_hh1) {
    int gid = blockIdx.x * 256 + threadIdx.x;        // 393216
    int ntile = gid / 24576;
    int rem   = gid % 24576;
    int chunk = rem >> 12;                           // 0,1:L0  2..5:L1
    int r2    = rem & 4095;
    int ks    = r2 >> 9;
    int nt    = (r2 >> 6) & 7;
    int lane  = (r2 >> 1) & 31;
    int e     = r2 & 1;
    int c     = nt * 8 + (lane >> 2);
    int srow  = col2row(ntile, c);
    int kb    = (chunk < 2) ? chunk * 128 : (chunk - 2) * 128;
    uint32_t w = 0;
    #pragma unroll
    for (int j = 0; j < 2; j++) {
        int kg = kb + ks * 16 + (lane & 3) * 2 + j + e * 8;
        float v;
        if (chunk < 2) v = w_hh0[srow * 256 + kg];
        else v = (kg < 256) ? w_ih1[srow * 256 + kg] : w_hh1[srow * 256 + kg - 256];
        __half h = __float2half_rn(v);
        w |= (uint32_t)(*(uint16_t*)&h) << (16 * j);
    }
    g_wf[gid] = w;
}

__global__ void prep_misc(const float* __restrict__ w_out,
                          const float* __restrict__ b_ih1,
                          const float* __restrict__ b_hh1) {
    int idx = blockIdx.x * 256 + threadIdx.x;        // 16384
    int o = idx & 63, u = idx >> 6;
    g_wotp[u * 64 + o] = w_out[o * 256 + u];
    if (idx < 1024) {
        int ntile = idx >> 6, c = idx & 63;
        int srow = col2row(ntile, c);
        g_b1p[idx] = b_ih1[srow] + b_hh1[srow];
    }
    if (idx < 8) g_barm[idx] = 0;
}

__global__ void prep_init(const float* __restrict__ latent,
                          const float* __restrict__ w_lh, const float* __restrict__ b_lh,
                          const float* __restrict__ w_lc, const float* __restrict__ b_lc,
                          const float* __restrict__ w_ih0, const float* __restrict__ b_ih0,
                          const float* __restrict__ b_hh0) {
    __shared__ float lat[LATD];
    const int b = blockIdx.x, t = threadIdx.x;
    if (t < LATD) lat[t] = latent[b * LATD + t];
    __syncthreads();

    #pragma unroll
    for (int g = 0; g < 4; g++) {
        int n = g * 256 + t;
        const float4* wr = (const float4*)(w_ih0 + n * LATD);
        float acc = b_ih0[n] + b_hh0[n];
        #pragma unroll 8
        for (int q = 0; q < LATD / 4; q++) {
            float4 w4 = __ldg(wr + q);
            acc += lat[4*q]*w4.x + lat[4*q+1]*w4.y + lat[4*q+2]*w4.z + lat[4*q+3]*w4.w;
        }
        // permuted col: unit t, gate g
        int colp = (t >> 4) * 64 + (g >> 1) * 32 + ((t >> 2) & 3) * 8 + (t & 3) * 2 + (g & 1);
        g_gx0p[b * 1024 + colp] = acc;
    }
    #pragma unroll
    for (int half = 0; half < 2; half++) {
        float hv, cv;
        {
            const float4* wr = (const float4*)(w_lh + (half * 256 + t) * LATD);
            float acc = b_lh[half * 256 + t];
            #pragma unroll 8
            for (int q = 0; q < LATD / 4; q++) {
                float4 w4 = __ldg(wr + q);
                acc += lat[4*q]*w4.x + lat[4*q+1]*w4.y + lat[4*q+2]*w4.z + lat[4*q+3]*w4.w;
            }
            hv = acc;
        }
        {
            const float4* wr = (const float4*)(w_lc + (half * 256 + t) * LATD);
            float acc = b_lc[half * 256 + t];
            #pragma unroll 8
            for (int q = 0; q < LATD / 4; q++) {
                float4 w4 = __ldg(wr + q);
                acc += lat[4*q]*w4.x + lat[4*q+1]*w4.y + lat[4*q+2]*w4.z + lat[4*q+3]*w4.w;
            }
            cv = acc;
        }
        int p = HB + b * 256 + t;                    // initial h -> buffer 1
        if (half == 0) g_h0f[p] = __float2half_rn(hv);
        else           g_h1f[p] = __float2half_rn(hv);
        g_cinit[b * 512 + half * 256 + t] = cv;
    }
}

// ================= main kernel pieces =================
// per-mtile barrier: 16 CTAs per group
__device__ __forceinline__ void gbarm(int tid, int mtile, unsigned target) {
    __threadfence();
    __syncthreads();
    if (tid == 0) {
        atomicAdd(&g_barm[mtile], 1u);
        unsigned v;
        do {
            asm volatile("ld.acquire.gpu.global.u32 %0, [%1];" : "=r"(v) : "l"(&g_barm[mtile]) : "memory");
        } while (v < target);
    }
    __syncthreads();
}

// async-copy one 128x128 fp16 chunk (cols kofs..kofs+127) into padded A tile.
// 2048 x 16B = 128 rows x 16 segments.
__device__ __forceinline__ void fill_async(uint32_t sdst, const __half* src, int kofs, int tid) {
    const uint4* s4 = (const uint4*)(src + kofs);    // row stride 512B = 32 uint4
    #pragma unroll
    for (int it = 0; it < 8; it++) {
        int i = tid + it * 256;
        int r = i >> 4, seg = i & 15;
        cpa16(sdst + r * 272 + seg * 16, s4 + r * 32 + seg);
    }
}

// one GEMM pass over a K=128 chunk: 8 k-steps x 8 n-tiles (fp16 single pass)
__device__ __forceinline__ void gemm_pass(uint32_t at_warp, uint32_t wf, float acc[8][4], int lane) {
    #pragma unroll
    for (int ks = 0; ks < 8; ks++) {
        uint32_t a0, a1, a2, a3;
        uint32_t aaddr = at_warp + (lane & 15) * 272 + ks * 32 + (lane >> 4) * 16;
        asm volatile("ldmatrix.sync.aligned.m8n8.x4.shared.b16 {%0,%1,%2,%3}, [%4];"
                     : "=r"(a0), "=r"(a1), "=r"(a2), "=r"(a3) : "r"(aaddr));
        #pragma unroll
        for (int nt = 0; nt < 8; nt++) {
            uint32_t b0, b1;
            uint32_t baddr = wf + ((ks * 8 + nt) * 32 + lane) * 8;
            asm volatile("ld.shared.v2.u32 {%0,%1}, [%2];" : "=r"(b0), "=r"(b1) : "r"(baddr));
            asm volatile(
                "mma.sync.aligned.m16n8k16.row.col.f32.f16.f16.f32 "
                "{%0,%1,%2,%3}, {%4,%5,%6,%7}, {%8,%9}, {%0,%1,%2,%3};"
                : "+f"(acc[nt][0]), "+f"(acc[nt][1]), "+f"(acc[nt][2]), "+f"(acc[nt][3])
                : "r"(a0), "r"(a1), "r"(a2), "r"(a3), "r"(b0), "r"(b1));
        }
    }
}

__device__ __forceinline__ void cell_pub(float acc[8][4], float* c, float* hn,
                                         __half* gh, int rbase, int ntile, int lane) {
    #pragma unroll
    for (int nt_ = 0; nt_ < 4; nt_++) {
        #pragma unroll
        for (int rh = 0; rh < 2; rh++) {
            int i = nt_ * 2 + rh;
            float gi = acc[nt_][rh * 2],     gf = acc[nt_][rh * 2 + 1];
            float gg = acc[nt_ + 4][rh * 2], go = acc[nt_ + 4][rh * 2 + 1];
            float cn = sigf(gf) * c[i] + sigf(gi) * tanhf_(gg);
            c[i] = cn;
            float h = sigf(go) * tanhf_(cn);
            hn[i] = h;
            int rowg = rbase + rh * 8;
            int ug = ntile * 16 + nt_ * 4 + (lane & 3);
            stg16(gh + rowg * 256 + ug, __float2half_rn(h));
        }
    }
}

__global__ void __launch_bounds__(256, 1)
lstm_mma(const float* __restrict__ b_out, float* __restrict__ out) {
    extern __shared__ char smem[];
    const int tid = threadIdx.x, wid = tid >> 5, lane = tid & 31;
    const int mtile = blockIdx.x >> 4, ntile = blockIdx.x & 15;
    const uint32_t sbase = s2u(smem);
    const uint32_t at0 = sbase + SM_AT0, at1 = sbase + SM_AT1;
    const uint32_t at0w = at0 + wid * 16 * 272, at1w = at1 + wid * 16 * 272;
    const int rbase = mtile * 128 + wid * 16 + (lane >> 2);
    const int hoff = mtile * 128 * 256;

    // weight fragments -> SMEM
    {
        const uint4* sh = (const uint4*)(g_wf + ntile * 24576);
        uint4* dh = (uint4*)(smem + SM_WF);
        for (int i = tid; i < 6144; i += 256) dh[i] = __ldg(sh + i);
    }

    // per-lane constants
    float gx[8][4], b1r[8][2];
    #pragma unroll
    for (int nt = 0; nt < 8; nt++) {
        #pragma unroll
        for (int r = 0; r < 4; r++) {
            int rowg = rbase + (r >> 1) * 8;
            int c = nt * 8 + 2 * (lane & 3) + (r & 1);
            gx[nt][r] = __ldg(&g_gx0p[rowg * 1024 + ntile * 64 + c]);
        }
        b1r[nt][0] = __ldg(&g_b1p[ntile * 64 + nt * 8 + 2 * (lane & 3)]);
        b1r[nt][1] = __ldg(&g_b1p[ntile * 64 + nt * 8 + 2 * (lane & 3) + 1]);
    }
    float c0[8], c1[8];
    #pragma unroll
    for (int i = 0; i < 8; i++) {
        int rowg = rbase + (i & 1) * 8;
        int ug = ntile * 16 + (i >> 1) * 4 + (lane & 3);
        c0[i] = __ldg(&g_cinit[rowg * 512 + ug]);
        c1[i] = __ldg(&g_cinit[rowg * 512 + 256 + ug]);
    }
    __syncthreads();

    unsigned tgt = 16;
    float acc[8][4];

    #pragma unroll 1
    for (int s = 0; s < TT; s++) {
        const int wb = s & 1, rb = wb ^ 1;
        const __half* h0p = g_h0f + rb * HB + hoff;
        const __half* h1p = g_h1f + rb * HB + hoff;
        const __half* h0n_g = g_h0f + wb * HB + hoff;

        // ---------------- layer 0: fills for both chunks, one wait ----------------
        fill_async(at0, h0p, 0, tid);
        fill_async(at1, h0p, 128, tid);
        CP_COMMIT();

        // out reduction for step s-1 (overlaps the cp.async fills)
        if (s > 0 && tid < 128) {
            int rowg = mtile * 128 + tid;
            float4 a = __ldg((const float4*)(b_out + ntile * 4));
            #pragma unroll
            for (int nt = 0; nt < 16; nt++) {
                uint4 v = ldcg4(&g_opart[(nt * 1024 + rowg) * 64 + ntile * 4]);
                a.x += __uint_as_float(v.x); a.y += __uint_as_float(v.y);
                a.z += __uint_as_float(v.z); a.w += __uint_as_float(v.w);
            }
            *(float4*)&out[(rowg * TT + s - 1) * OUTD + ntile * 4] = a;
        }

        CP_WAIT0();
        __syncthreads();

        #pragma unroll
        for (int nt = 0; nt < 8; nt++)
            #pragma unroll
            for (int r = 0; r < 4; r++) acc[nt][r] = gx[nt][r];
        gemm_pass(at0w, sbase + SM_WF + 0 * 16384, acc, lane);
        gemm_pass(at1w, sbase + SM_WF + 1 * 16384, acc, lane);

        float h0n[8];
        cell_pub(acc, c0, h0n, g_h0f + wb * HB, rbase, ntile, lane);

        __syncthreads();                              // all warps done with A bufs
        // prefetch h1_prev chunks (independent of barrier A) -> overlap barrier spin
        fill_async(at0, h1p, 0, tid);
        fill_async(at1, h1p, 128, tid);
        CP_COMMIT();

        gbarm(tid, mtile, tgt); tgt += 16;            // barrier A: h0_new visible

        CP_WAIT0();
        __syncthreads();

        // ---------------- layer 1: h1_prev part first ----------------
        #pragma unroll
        for (int nt = 0; nt < 8; nt++) {
            acc[nt][0] = b1r[nt][0]; acc[nt][1] = b1r[nt][1];
            acc[nt][2] = b1r[nt][0]; acc[nt][3] = b1r[nt][1];
        }
        gemm_pass(at0w, sbase + SM_WF + 4 * 16384, acc, lane);
        gemm_pass(at1w, sbase + SM_WF + 5 * 16384, acc, lane);

        __syncthreads();
        fill_async(at0, h0n_g, 0, tid);
        fill_async(at1, h0n_g, 128, tid);
        CP_COMMIT();
        CP_WAIT0();
        __syncthreads();

        gemm_pass(at0w, sbase + SM_WF + 2 * 16384, acc, lane);
        gemm_pass(at1w, sbase + SM_WF + 3 * 16384, acc, lane);

        float h1n[8];
        cell_pub(acc, c1, h1n, g_h1f + wb * HB, rbase, ntile, lane);

        // out partials: lane (a = lane&3) computes outs [a*16, a*16+16) for its 2 rows
        {
            float po0[16], po1[16];
            #pragma unroll
            for (int o = 0; o < 16; o++) { po0[o] = 0.f; po1[o] = 0.f; }
            #pragma unroll
            for (int uu = 0; uu < 16; uu++) {
                float hv0 = __shfl_sync(0xffffffffu, h1n[(uu >> 2) * 2],     uu & 3, 4);
                float hv1 = __shfl_sync(0xffffffffu, h1n[(uu >> 2) * 2 + 1], uu & 3, 4);
                const float4* wr = (const float4*)(g_wotp + (ntile * 16 + uu) * 64 + (lane & 3) * 16);
                #pragma unroll
                for (int q = 0; q < 4; q++) {
                    float4 w = __ldg(wr + q);
                    po0[q*4+0] += hv0 * w.x; po0[q*4+1] += hv0 * w.y;
                    po0[q*4+2] += hv0 * w.z; po0[q*4+3] += hv0 * w.w;
                    po1[q*4+0] += hv1 * w.x; po1[q*4+1] += hv1 * w.y;
                    po1[q*4+2] += hv1 * w.z; po1[q*4+3] += hv1 * w.w;
                }
            }
            float* p0 = &g_opart[(ntile * 1024 + rbase) * 64 + (lane & 3) * 16];
            float* p1 = &g_opart[(ntile * 1024 + rbase + 8) * 64 + (lane & 3) * 16];
            #pragma unroll
            for (int q = 0; q < 4; q++) {
                stcg4(p0 + q * 4, make_uint4(__float_as_uint(po0[q*4]),   __float_as_uint(po0[q*4+1]),
                                             __float_as_uint(po0[q*4+2]), __float_as_uint(po0[q*4+3])));
                stcg4(p1 + q * 4, make_uint4(__float_as_uint(po1[q*4]),   __float_as_uint(po1[q*4+1]),
                                             __float_as_uint(po1[q*4+2]), __float_as_uint(po1[q*4+3])));
            }
        }
        gbarm(tid, mtile, tgt); tgt += 16;            // barrier B: h1_new + partials visible
    }

    // final out reduction (step TT-1)
    if (tid < 128) {
        int rowg = mtile * 128 + tid;
        float4 a = __ldg((const float4*)(b_out + ntile * 4));
        #pragma unroll
        for (int nt = 0; nt < 16; nt++) {
            uint4 v = ldcg4(&g_opart[(nt * 1024 + rowg) * 64 + ntile * 4]);
            a.x += __uint_as_float(v.x); a.y += __uint_as_float(v.y);
            a.z += __uint_as_float(v.z); a.w += __uint_as_float(v.w);
        }
        *(float4*)&out[(rowg * TT + TT - 1) * OUTD + ntile * 4] = a;
    }
}

// ================= launch =================
extern "C" void kernel_launch(void* const* d_in, const int* in_sizes, int n_in,
                              void* d_out, int out_size) {
    const float* latent = (const float*)d_in[0];
    const float* w_lh   = (const float*)d_in[1];
    const float* b_lh   = (const float*)d_in[2];
    const float* w_lc   = (const float*)d_in[3];
    const float* b_lc   = (const float*)d_in[4];
    const float* w_ih0  = (const float*)d_in[5];
    const float* w_hh0  = (const float*)d_in[6];
    const float* b_ih0  = (const float*)d_in[7];
    const float* b_hh0  = (const float*)d_in[8];
    const float* w_ih1  = (const float*)d_in[9];
    const float* w_hh1  = (const float*)d_in[10];
    const float* b_ih1  = (const float*)d_in[11];
    const float* b_hh1  = (const float*)d_in[12];
    const float* w_out  = (const float*)d_in[13];
    const float* b_out  = (const float*)d_in[14];
    float* out = (float*)d_out;

    cudaFuncSetAttribute(lstm_mma, cudaFuncAttributeMaxDynamicSharedMemorySize, SMEM_SZ);

    prep_wfrag<<<1536, 256>>>(w_hh0, w_ih1, w_hh1);
    prep_misc<<<64, 256>>>(w_out, b_ih1, b_hh1);
    prep_init<<<BATCH, 256>>>(latent, w_lh, b_lh, w_lc, b_lc, w_ih0, b_ih0, b_hh0);
    lstm_mma<<<128, 256, SMEM_SZ>>>(b_out, out);
}

// round 15
// speedup vs baseline: 4.2236x; 1.5541x over previous
#include <cuda_runtime.h>
#include <cuda_fp16.h>
#include <cstdint>

#define TT    256
#define BATCH 1024
#define LATD  128
#define OUTD  64
#define HB    (BATCH * 256)

// SMEM layout (bytes)
#define SM_WF 0          // 98304: B-fragments fp16, [6 chunks][64 slots][32 lanes] uint2
#define SM_P  98304      // 65536: A tile P (h0), 2 chunks x 32768, 256B stride XOR-swizzled
#define SM_Q  163840     // 65536: A tile Q (h1)
#define SMEM_SZ 229376

// ---------------- static device scratch (no allocations) ----------------
__device__ uint32_t g_wf[393216];                    // [ntile][6][64][32][2] uint32 (fp16x2)
__device__ uint2 g_wof[16 * 2 * 8 * 32];             // out-proj fragments [nt][ch][ks][lane]
__device__ float g_b1p[1024];                        // permuted bias1
__device__ float g_gx0p[BATCH * 1024];               // [b][permuted col]
__device__ float g_cinit[BATCH * 512];               // [b][layer*256+unit]
__device__ __half g_h0f[2 * HB], g_h1f[2 * HB];      // double-buffered fp16 h
__device__ unsigned g_barm[8];                       // per-mtile barrier counters

// ---------------- helpers ----------------
__device__ __forceinline__ uint32_t s2u(const void* p) {
    uint32_t a;
    asm("{ .reg .u64 t; cvta.to.shared.u64 t, %1; cvt.u32.u64 %0, t; }" : "=r"(a) : "l"(p));
    return a;
}
__device__ __forceinline__ void stg16(__half* p, __half v) {
    unsigned short u = *(unsigned short*)&v;
    asm volatile("st.global.cg.u16 [%0], %1;" :: "l"(p), "h"(u) : "memory");
}
__device__ __forceinline__ void cpa16(uint32_t saddr, const void* gptr) {
    asm volatile("cp.async.cg.shared.global [%0], [%1], 16;" :: "r"(saddr), "l"(gptr) : "memory");
}
#define CP_COMMIT() asm volatile("cp.async.commit_group;" ::: "memory")
#define CP_WAIT0()  asm volatile("cp.async.wait_group 0;" ::: "memory")
#define CP_WAIT1()  asm volatile("cp.async.wait_group 1;" ::: "memory")

__device__ __forceinline__ float sigf(float x) { return __fdividef(1.f, 1.f + __expf(-x)); }
__device__ __forceinline__ float tanhf_(float x) {
    x = fminf(fmaxf(x, -15.f), 15.f);
    float e = __expf(2.f * x);
    return __fdividef(e - 1.f, e + 1.f);
}
// permuted column -> original gate row. col c of a CTA: gate=(c>>5)*2+(c&1),
// unit_local = ((c>>3)&3)*4 + ((c>>1)&3)
__device__ __forceinline__ int col2row(int ntile, int c) {
    int g = (c >> 5) * 2 + (c & 1);
    int u = ((c >> 3) & 3) * 4 + ((c >> 1) & 3);
    return g * 256 + ntile * 16 + u;
}

// ================= prep kernels =================
// B fragments in exact mma.sync n8k16 per-lane layout: lane holds b[k,n],
// n = nt*8 + (lane>>2), k = (lane&3)*2 + j + e*8.
__global__ void prep_wfrag(const float* __restrict__ w_hh0,
                           const float* __restrict__ w_ih1,
                           const float* __restrict__ w_hh1) {
    int gid = blockIdx.x * 256 + threadIdx.x;        // 393216
    int ntile = gid / 24576;
    int rem   = gid % 24576;
    int chunk = rem >> 12;                           // 0,1:L0  2..5:L1
    int r2    = rem & 4095;
    int ks    = r2 >> 9;
    int nt    = (r2 >> 6) & 7;
    int lane  = (r2 >> 1) & 31;
    int e     = r2 & 1;
    int c     = nt * 8 + (lane >> 2);
    int srow  = col2row(ntile, c);
    int kb    = (chunk < 2) ? chunk * 128 : (chunk - 2) * 128;
    uint32_t w = 0;
    #pragma unroll
    for (int j = 0; j < 2; j++) {
        int kg = kb + ks * 16 + (lane & 3) * 2 + j + e * 8;
        float v;
        if (chunk < 2) v = w_hh0[srow * 256 + kg];
        else v = (kg < 256) ? w_ih1[srow * 256 + kg] : w_hh1[srow * 256 + kg - 256];
        __half h = __float2half_rn(v);
        w |= (uint32_t)(*(uint16_t*)&h) << (16 * j);
    }
    g_wf[gid] = w;
}

__global__ void prep_misc(const float* __restrict__ w_out,
                          const float* __restrict__ b_ih1,
                          const float* __restrict__ b_hh1) {
    int idx = blockIdx.x * 256 + threadIdx.x;        // 16384
    // out-proj fragments: [nt][ch][ks][lane]; lane holds b[k,n], n=lane>>2 (n<4 real)
    if (idx < 8192) {
        int lane = idx & 31, ks = (idx >> 5) & 7, ch = (idx >> 8) & 1, nt = idx >> 9;
        int n = lane >> 2;
        uint2 w = make_uint2(0u, 0u);
        if (n < 4) {
            int col = nt * 4 + n;
            uint32_t pk[2];
            #pragma unroll
            for (int e = 0; e < 2; e++) {
                uint32_t v = 0;
                #pragma unroll
                for (int j = 0; j < 2; j++) {
                    int k = ch * 128 + ks * 16 + (lane & 3) * 2 + j + e * 8;
                    __half h = __float2half_rn(w_out[col * 256 + k]);
                    v |= (uint32_t)(*(uint16_t*)&h) << (16 * j);
                }
                pk[e] = v;
            }
            w = make_uint2(pk[0], pk[1]);
        }
        g_wof[idx] = w;
    }
    if (idx < 1024) {
        int ntile = idx >> 6, c = idx & 63;
        int srow = col2row(ntile, c);
        g_b1p[idx] = b_ih1[srow] + b_hh1[srow];
    }
    if (idx < 8) g_barm[idx] = 0;
}

__global__ void prep_init(const float* __restrict__ latent,
                          const float* __restrict__ w_lh, const float* __restrict__ b_lh,
                          const float* __restrict__ w_lc, const float* __restrict__ b_lc,
                          const float* __restrict__ w_ih0, const float* __restrict__ b_ih0,
                          const float* __restrict__ b_hh0) {
    __shared__ float lat[LATD];
    const int b = blockIdx.x, t = threadIdx.x;
    if (t < LATD) lat[t] = latent[b * LATD + t];
    __syncthreads();

    #pragma unroll
    for (int g = 0; g < 4; g++) {
        int n = g * 256 + t;
        const float4* wr = (const float4*)(w_ih0 + n * LATD);
        float acc = b_ih0[n] + b_hh0[n];
        #pragma unroll 8
        for (int q = 0; q < LATD / 4; q++) {
            float4 w4 = __ldg(wr + q);
            acc += lat[4*q]*w4.x + lat[4*q+1]*w4.y + lat[4*q+2]*w4.z + lat[4*q+3]*w4.w;
        }
        // permuted col: unit t, gate g
        int colp = (t >> 4) * 64 + (g >> 1) * 32 + ((t >> 2) & 3) * 8 + (t & 3) * 2 + (g & 1);
        g_gx0p[b * 1024 + colp] = acc;
    }
    #pragma unroll
    for (int half = 0; half < 2; half++) {
        float hv, cv;
        {
            const float4* wr = (const float4*)(w_lh + (half * 256 + t) * LATD);
            float acc = b_lh[half * 256 + t];
            #pragma unroll 8
            for (int q = 0; q < LATD / 4; q++) {
                float4 w4 = __ldg(wr + q);
                acc += lat[4*q]*w4.x + lat[4*q+1]*w4.y + lat[4*q+2]*w4.z + lat[4*q+3]*w4.w;
            }
            hv = acc;
        }
        {
            const float4* wr = (const float4*)(w_lc + (half * 256 + t) * LATD);
            float acc = b_lc[half * 256 + t];
            #pragma unroll 8
            for (int q = 0; q < LATD / 4; q++) {
                float4 w4 = __ldg(wr + q);
                acc += lat[4*q]*w4.x + lat[4*q+1]*w4.y + lat[4*q+2]*w4.z + lat[4*q+3]*w4.w;
            }
            cv = acc;
        }
        int p = HB + b * 256 + t;                    // initial h -> buffer 1
        if (half == 0) g_h0f[p] = __float2half_rn(hv);
        else           g_h1f[p] = __float2half_rn(hv);
        g_cinit[b * 512 + half * 256 + t] = cv;
    }
}

// ================= main kernel pieces =================
// per-mtile barrier: 16 CTAs per group
__device__ __forceinline__ void gbarm(int tid, int mtile, unsigned target) {
    __threadfence();
    __syncthreads();
    if (tid == 0) {
        atomicAdd(&g_barm[mtile], 1u);
        unsigned v;
        do {
            asm volatile("ld.acquire.gpu.global.u32 %0, [%1];" : "=r"(v) : "l"(&g_barm[mtile]) : "memory");
        } while (v < target);
    }
    __syncthreads();
}

// async-copy one 128x128 fp16 chunk into XOR-swizzled 256B-stride A tile
__device__ __forceinline__ void fill_async(uint32_t sdst, const __half* src, int kofs, int tid) {
    const uint4* s4 = (const uint4*)(src + kofs);    // row stride 512B = 32 uint4
    #pragma unroll
    for (int it = 0; it < 8; it++) {
        int i = tid + it * 256;
        int r = i >> 4, seg = i & 15;
        cpa16(sdst + r * 256 + ((seg ^ (r & 7)) << 4), s4 + r * 32 + seg);
    }
}

// one GEMM pass over a K=128 chunk: 8 k-steps x 8 n-tiles (fp16)
__device__ __forceinline__ void gemm_pass(uint32_t at_warp, uint32_t wf, float acc[8][4], int lane) {
    #pragma unroll
    for (int ks = 0; ks < 8; ks++) {
        uint32_t a0, a1, a2, a3;
        uint32_t row = lane & 15;
        uint32_t seg = (uint32_t)(ks * 2) + (uint32_t)(lane >> 4);
        uint32_t aaddr = at_warp + row * 256 + ((seg ^ (row & 7)) << 4);
        asm volatile("ldmatrix.sync.aligned.m8n8.x4.shared.b16 {%0,%1,%2,%3}, [%4];"
                     : "=r"(a0), "=r"(a1), "=r"(a2), "=r"(a3) : "r"(aaddr));
        #pragma unroll
        for (int nt = 0; nt < 8; nt++) {
            uint32_t b0, b1;
            uint32_t baddr = wf + ((ks * 8 + nt) * 32 + lane) * 8;
            asm volatile("ld.shared.v2.u32 {%0,%1}, [%2];" : "=r"(b0), "=r"(b1) : "r"(baddr));
            asm volatile(
                "mma.sync.aligned.m16n8k16.row.col.f32.f16.f16.f32 "
                "{%0,%1,%2,%3}, {%4,%5,%6,%7}, {%8,%9}, {%0,%1,%2,%3};"
                : "+f"(acc[nt][0]), "+f"(acc[nt][1]), "+f"(acc[nt][2]), "+f"(acc[nt][3])
                : "r"(a0), "r"(a1), "r"(a2), "r"(a3), "r"(b0), "r"(b1));
        }
    }
}

// out projection for this CTA's 4 cols from the Q tile (h1), rows = mtile's 128
__device__ __forceinline__ void outproj(uint32_t Qw0, uint32_t Qw1, const uint2* wofp,
                                        float bo0, float bo1, float* __restrict__ out,
                                        int so, int rbase, int ntile, int lane) {
    float oa[4] = {0.f, 0.f, 0.f, 0.f};
    #pragma unroll
    for (int ch = 0; ch < 2; ch++) {
        uint32_t qb = ch ? Qw1 : Qw0;
        #pragma unroll
        for (int ks = 0; ks < 8; ks++) {
            uint32_t a0, a1, a2, a3;
            uint32_t row = lane & 15;
            uint32_t seg = (uint32_t)(ks * 2) + (uint32_t)(lane >> 4);
            uint32_t aaddr = qb + row * 256 + ((seg ^ (row & 7)) << 4);
            asm volatile("ldmatrix.sync.aligned.m8n8.x4.shared.b16 {%0,%1,%2,%3}, [%4];"
                         : "=r"(a0), "=r"(a1), "=r"(a2), "=r"(a3) : "r"(aaddr));
            uint2 bb = __ldg(wofp + ch * 256 + ks * 32);
            asm volatile(
                "mma.sync.aligned.m16n8k16.row.col.f32.f16.f16.f32 "
                "{%0,%1,%2,%3}, {%4,%5,%6,%7}, {%8,%9}, {%0,%1,%2,%3};"
                : "+f"(oa[0]), "+f"(oa[1]), "+f"(oa[2]), "+f"(oa[3])
                : "r"(a0), "r"(a1), "r"(a2), "r"(a3), "r"(bb.x), "r"(bb.y));
        }
    }
    if ((lane & 3) < 2) {
        int co = ntile * 4 + 2 * (lane & 3);
        float2 v0 = make_float2(oa[0] + bo0, oa[1] + bo1);
        float2 v1 = make_float2(oa[2] + bo0, oa[3] + bo1);
        *(float2*)&out[(rbase * TT + so) * OUTD + co] = v0;
        *(float2*)&out[((rbase + 8) * TT + so) * OUTD + co] = v1;
    }
}

__device__ __forceinline__ void cell_pub(float acc[8][4], float* c, float* hn,
                                         __half* gh, int rbase, int ntile, int lane) {
    #pragma unroll
    for (int nt_ = 0; nt_ < 4; nt_++) {
        #pragma unroll
        for (int rh = 0; rh < 2; rh++) {
            int i = nt_ * 2 + rh;
            float gi = acc[nt_][rh * 2],     gf = acc[nt_][rh * 2 + 1];
            float gg = acc[nt_ + 4][rh * 2], go = acc[nt_ + 4][rh * 2 + 1];
            float cn = sigf(gf) * c[i] + sigf(gi) * tanhf_(gg);
            c[i] = cn;
            float h = sigf(go) * tanhf_(cn);
            hn[i] = h;
            int rowg = rbase + rh * 8;
            int ug = ntile * 16 + nt_ * 4 + (lane & 3);
            stg16(gh + rowg * 256 + ug, __float2half_rn(h));
        }
    }
}

__global__ void __launch_bounds__(256, 1)
lstm_mma(const float* __restrict__ b_out, float* __restrict__ out) {
    extern __shared__ char smem[];
    const int tid = threadIdx.x, wid = tid >> 5, lane = tid & 31;
    const int mtile = blockIdx.x >> 4, ntile = blockIdx.x & 15;
    const uint32_t sbase = s2u(smem);
    const uint32_t P = sbase + SM_P, Q = sbase + SM_Q;
    const uint32_t Pw0 = P + wid * 4096, Pw1 = P + 32768 + wid * 4096;
    const uint32_t Qw0 = Q + wid * 4096, Qw1 = Q + 32768 + wid * 4096;
    const int rbase = mtile * 128 + wid * 16 + (lane >> 2);
    const int hoff = mtile * 128 * 256;

    // weight fragments -> SMEM
    {
        const uint4* sh = (const uint4*)(g_wf + ntile * 24576);
        uint4* dh = (uint4*)(smem + SM_WF);
        for (int i = tid; i < 6144; i += 256) dh[i] = __ldg(sh + i);
    }

    // per-lane constants
    float gx[8][4], b1r[8][2];
    #pragma unroll
    for (int nt = 0; nt < 8; nt++) {
        #pragma unroll
        for (int r = 0; r < 4; r++) {
            int rowg = rbase + (r >> 1) * 8;
            int c = nt * 8 + 2 * (lane & 3) + (r & 1);
            gx[nt][r] = __ldg(&g_gx0p[rowg * 1024 + ntile * 64 + c]);
        }
        b1r[nt][0] = __ldg(&g_b1p[ntile * 64 + nt * 8 + 2 * (lane & 3)]);
        b1r[nt][1] = __ldg(&g_b1p[ntile * 64 + nt * 8 + 2 * (lane & 3) + 1]);
    }
    float c0[8], c1[8];
    #pragma unroll
    for (int i = 0; i < 8; i++) {
        int rowg = rbase + (i & 1) * 8;
        int ug = ntile * 16 + (i >> 1) * 4 + (lane & 3);
        c0[i] = __ldg(&g_cinit[rowg * 512 + ug]);
        c1[i] = __ldg(&g_cinit[rowg * 512 + 256 + ug]);
    }
    float bo0 = 0.f, bo1 = 0.f;
    if ((lane & 3) < 2) {
        bo0 = __ldg(&b_out[ntile * 4 + 2 * (lane & 3)]);
        bo1 = __ldg(&b_out[ntile * 4 + 2 * (lane & 3) + 1]);
    }
    const uint2* wofp = g_wof + ntile * 512 + lane;
    __syncthreads();

    // pre-fill P with h0_init (buffer 1)
    fill_async(P,         g_h0f + HB + hoff, 0,   tid);
    fill_async(P + 32768, g_h0f + HB + hoff, 128, tid);
    CP_COMMIT();
    CP_WAIT0();
    __syncthreads();

    unsigned tgt = 16;
    float acc[8][4];

    #pragma unroll 1
    for (int s = 0; s < TT; s++) {
        const int wb = s & 1, rb = wb ^ 1;

        // prefetch Q <- h1_prev (overlaps layer-0 GEMM; P already resident)
        fill_async(Q,         g_h1f + rb * HB + hoff, 0,   tid);
        fill_async(Q + 32768, g_h1f + rb * HB + hoff, 128, tid);
        CP_COMMIT();

        // ---------------- layer 0 on resident P ----------------
        #pragma unroll
        for (int nt = 0; nt < 8; nt++)
            #pragma unroll
            for (int r = 0; r < 4; r++) acc[nt][r] = gx[nt][r];
        gemm_pass(Pw0, sbase + SM_WF + 0 * 16384, acc, lane);
        gemm_pass(Pw1, sbase + SM_WF + 1 * 16384, acc, lane);

        float h0n[8];
        cell_pub(acc, c0, h0n, g_h0f + wb * HB, rbase, ntile, lane);

        gbarm(tid, mtile, tgt); tgt += 16;            // barrier A: h0_new visible

        // refill P <- h0_new (hidden under W1b + outproj below); P also serves next step's L0
        fill_async(P,         g_h0f + wb * HB + hoff, 0,   tid);
        fill_async(P + 32768, g_h0f + wb * HB + hoff, 128, tid);
        CP_COMMIT();

        CP_WAIT1();                                   // Q done (P may still fly)
        __syncthreads();

        // ---------------- layer 1: h1_prev part on Q ----------------
        #pragma unroll
        for (int nt = 0; nt < 8; nt++) {
            acc[nt][0] = b1r[nt][0]; acc[nt][1] = b1r[nt][1];
            acc[nt][2] = b1r[nt][0]; acc[nt][3] = b1r[nt][1];
        }
        gemm_pass(Qw0, sbase + SM_WF + 4 * 16384, acc, lane);
        gemm_pass(Qw1, sbase + SM_WF + 5 * 16384, acc, lane);

        // out projection for step s-1 (Q holds h1_new(s-1))
        if (s > 0)
            outproj(Qw0, Qw1, wofp, bo0, bo1, out, s - 1, rbase, ntile, lane);

        CP_WAIT0();                                   // P (h0_new) done
        __syncthreads();

        // ---------------- layer 1: h0_new part on P ----------------
        gemm_pass(Pw0, sbase + SM_WF + 2 * 16384, acc, lane);
        gemm_pass(Pw1, sbase + SM_WF + 3 * 16384, acc, lane);

        float h1n[8];
        cell_pub(acc, c1, h1n, g_h1f + wb * HB, rbase, ntile, lane);

        gbarm(tid, mtile, tgt); tgt += 16;            // barrier B: h1_new visible
    }

    // epilogue: out for step TT-1 (h1f buffer wb(TT-1) = 1)
    fill_async(Q,         g_h1f + HB + hoff, 0,   tid);
    fill_async(Q + 32768, g_h1f + HB + hoff, 128, tid);
    CP_COMMIT();
    CP_WAIT0();
    __syncthreads();
    outproj(Qw0, Qw1, wofp, bo0, bo1, out, TT - 1, rbase, ntile, lane);
}

// ================= launch =================
extern "C" void kernel_launch(void* const* d_in, const int* in_sizes, int n_in,
                              void* d_out, int out_size) {
    const float* latent = (const float*)d_in[0];
    const float* w_lh   = (const float*)d_in[1];
    const float* b_lh   = (const float*)d_in[2];
    const float* w_lc   = (const float*)d_in[3];
    const float* b_lc   = (const float*)d_in[4];
    const float* w_ih0  = (const float*)d_in[5];
    const float* w_hh0  = (const float*)d_in[6];
    const float* b_ih0  = (const float*)d_in[7];
    const float* b_hh0  = (const float*)d_in[8];
    const float* w_ih1  = (const float*)d_in[9];
    const float* w_hh1  = (const float*)d_in[10];
    const float* b_ih1  = (const float*)d_in[11];
    const float* b_hh1  = (const float*)d_in[12];
    const float* w_out  = (const float*)d_in[13];
    const float* b_out  = (const float*)d_in[14];
    float* out = (float*)d_out;

    cudaFuncSetAttribute(lstm_mma, cudaFuncAttributeMaxDynamicSharedMemorySize, SMEM_SZ);

    prep_wfrag<<<1536, 256>>>(w_hh0, w_ih1, w_hh1);
    prep_misc<<<64, 256>>>(w_out, b_ih1, b_hh1);
    prep_init<<<BATCH, 256>>>(latent, w_lh, b_lh, w_lc, b_lc, w_ih0, b_ih0, b_hh0);
    lstm_mma<<<128, 256, SMEM_SZ>>>(b_out, out);
}